// round 1
// baseline (speedup 1.0000x reference)
#include <cuda_runtime.h>
#include <cuda_bf16.h>

#define NN 100000
#define NE 1600000
#define DIN 256
#define DHID 64
#define DOUT 32
#define SCAN_BLOCK 1024
#define SCAN_NB ((NN + SCAN_BLOCK - 1) / SCAN_BLOCK)   // 98

// ---------------- scratch (static device memory: allowed) ----------------
__device__ float  g_x0[NN * DOUT];
__device__ float  g_xa[NN * DOUT];
__device__ float  g_xb[NN * DOUT];
__device__ float2 g_cv[NE];          // packed (col-as-int-bits, val)
__device__ int    g_offs[NN + 1];
__device__ int    g_deg[NN];
__device__ int    g_incl[NN];
__device__ int    g_cursor[NN];
__device__ int    g_bsum[128];

// ---------------- CSR build ----------------
__global__ void k_zero_deg() {
    int i = blockIdx.x * blockDim.x + threadIdx.x;
    if (i < NN) g_deg[i] = 0;
}

__global__ void k_hist(const int* __restrict__ row) {
    int e = blockIdx.x * blockDim.x + threadIdx.x;
    if (e < NE) atomicAdd(&g_deg[row[e]], 1);
}

__global__ void k_scan1() {
    __shared__ int s[SCAN_BLOCK];
    int t = threadIdx.x;
    int b = blockIdx.x;
    int i = b * SCAN_BLOCK + t;
    int v = (i < NN) ? g_deg[i] : 0;
    s[t] = v;
    __syncthreads();
    #pragma unroll
    for (int off = 1; off < SCAN_BLOCK; off <<= 1) {
        int add = (t >= off) ? s[t - off] : 0;
        __syncthreads();
        s[t] += add;
        __syncthreads();
    }
    if (i < NN) g_incl[i] = s[t];
    if (t == SCAN_BLOCK - 1) g_bsum[b] = s[t];
}

__global__ void k_scan2() {
    __shared__ int s[128];
    int t = threadIdx.x;
    s[t] = (t < SCAN_NB) ? g_bsum[t] : 0;
    __syncthreads();
    if (t == 0) {
        int run = 0;
        for (int b = 0; b < SCAN_NB; b++) { int tmp = s[b]; s[b] = run; run += tmp; }
    }
    __syncthreads();
    if (t < SCAN_NB) g_bsum[t] = s[t];
}

__global__ void k_scan3() {
    int i = blockIdx.x * blockDim.x + threadIdx.x;
    if (i < NN) {
        int inc = g_incl[i] + g_bsum[i >> 10];
        g_offs[i + 1] = inc;
        g_cursor[i]   = inc - g_deg[i];
        if (i == 0) g_offs[0] = 0;
    }
}

__global__ void k_fill(const int* __restrict__ row, const int* __restrict__ col,
                       const float* __restrict__ val) {
    int e = blockIdx.x * blockDim.x + threadIdx.x;
    if (e < NE) {
        int r = row[e];
        int p = atomicAdd(&g_cursor[r], 1);
        g_cv[p] = make_float2(__int_as_float(col[e]), val[e]);
    }
}

// ---------------- MLP head: x0 = relu(F@W1 + b1)@W2 + b2 ----------------
// block = 256 threads, thread-per-node. W1 (64KB) + W2 (8KB) + staging in dyn smem.
#define FPAD 33
__global__ void __launch_bounds__(256)
k_mlp(const float* __restrict__ features,
      const float* __restrict__ W1, const float* __restrict__ b1,
      const float* __restrict__ W2, const float* __restrict__ b2) {
    extern __shared__ float sm[];
    float* w1s = sm;                      // 16384
    float* w2s = sm + 16384;              // 2048
    float* b1s = w2s + 2048;              // 64
    float* b2s = b1s + 64;                // 32
    float* fsm = b2s + 32;                // 256*33 = 8448

    const int t = threadIdx.x;
    const int node0 = blockIdx.x * 256;
    const int myNode = node0 + t;
    const bool valid = (myNode < NN);

    for (int i = t; i < DIN * DHID; i += 256) w1s[i] = W1[i];
    for (int i = t; i < DHID * DOUT; i += 256) w2s[i] = W2[i];
    if (t < DHID) b1s[t] = b1[t];
    if (t < DOUT) b2s[t] = b2[t];
    __syncthreads();

    const float4* w1s4 = (const float4*)w1s;
    const float4* w2s4 = (const float4*)w2s;

    float acc[DHID];
    #pragma unroll
    for (int i = 0; i < DHID; i++) acc[i] = 0.f;

    // K loop in chunks of 32, features staged through smem
    for (int c = 0; c < DIN / 32; c++) {
        const int k0 = c * 32;
        __syncthreads();
        #pragma unroll
        for (int r = 0; r < 8; r++) {
            int lin = r * 256 + t;
            int nd = lin >> 3;
            int kg = lin & 7;
            float4 f4 = make_float4(0.f, 0.f, 0.f, 0.f);
            if (node0 + nd < NN)
                f4 = *(const float4*)&features[(size_t)(node0 + nd) * DIN + k0 + kg * 4];
            float* dst = &fsm[nd * FPAD + kg * 4];
            dst[0] = f4.x; dst[1] = f4.y; dst[2] = f4.z; dst[3] = f4.w;
        }
        __syncthreads();

        #pragma unroll 4
        for (int kk = 0; kk < 32; kk++) {
            float f = fsm[t * FPAD + kk];
            #pragma unroll
            for (int w = 0; w < 16; w++) {
                float4 wv = w1s4[(k0 + kk) * 16 + w];
                acc[w * 4 + 0] += f * wv.x;
                acc[w * 4 + 1] += f * wv.y;
                acc[w * 4 + 2] += f * wv.z;
                acc[w * 4 + 3] += f * wv.w;
            }
        }
    }

    // bias + relu
    #pragma unroll
    for (int i = 0; i < DHID; i++) {
        float z = acc[i] + b1s[i];
        acc[i] = z > 0.f ? z : 0.f;
    }

    // layer 2: out[32] = h @ W2 + b2, stage into fsm (row-private, no race with
    // own earlier reads; cross-thread consumption happens after the barrier)
    for (int jg = 0; jg < 8; jg++) {
        float4 sv = ((const float4*)b2s)[jg];
        #pragma unroll
        for (int l = 0; l < DHID; l++) {
            float4 wv = w2s4[l * 8 + jg];
            float h = acc[l];
            sv.x += h * wv.x; sv.y += h * wv.y;
            sv.z += h * wv.z; sv.w += h * wv.w;
        }
        float* dst = &fsm[t * FPAD + jg * 4];
        dst[0] = sv.x; dst[1] = sv.y; dst[2] = sv.z; dst[3] = sv.w;
    }
    __syncthreads();

    // coalesced write-out
    #pragma unroll
    for (int r = 0; r < 8; r++) {
        int lin = r * 256 + t;
        int nd = lin >> 3;
        int jg = lin & 7;
        if (node0 + nd < NN) {
            float4 o;
            const float* src = &fsm[nd * FPAD + jg * 4];
            o.x = src[0]; o.y = src[1]; o.z = src[2]; o.w = src[3];
            *(float4*)&g_x0[(size_t)(node0 + nd) * DOUT + jg * 4] = o;
        }
    }
}

// ---------------- propagation: dst = 0.9 * (A @ src) + 0.1 * x0 ----------------
// warp per node, lane = output column; one 128B coalesced line per edge gather.
__global__ void __launch_bounds__(256)
k_spmm(const float* __restrict__ xsrc, float* __restrict__ xdst) {
    int gtid = blockIdx.x * blockDim.x + threadIdx.x;
    int node = gtid >> 5;
    int lane = gtid & 31;
    if (node >= NN) return;

    int s = g_offs[node];
    int e = g_offs[node + 1];
    float acc = 0.f;
    for (int base = s; base < e; base += 32) {
        int idx = base + lane;
        float2 cv = make_float2(0.f, 0.f);
        if (idx < e) cv = g_cv[idx];
        int m = e - base; if (m > 32) m = 32;
        for (int j = 0; j < m; j++) {
            int   c = __float_as_int(__shfl_sync(0xffffffffu, cv.x, j));
            float v = __shfl_sync(0xffffffffu, cv.y, j);
            acc += v * __ldg(&xsrc[(size_t)c * DOUT + lane]);
        }
    }
    xdst[(size_t)node * DOUT + lane] = 0.9f * acc + 0.1f * g_x0[(size_t)node * DOUT + lane];
}

// ---------------- launch ----------------
extern "C" void kernel_launch(void* const* d_in, const int* in_sizes, int n_in,
                              void* d_out, int out_size) {
    const float* features = (const float*)d_in[0];
    const int*   row      = (const int*)d_in[1];
    const int*   col      = (const int*)d_in[2];
    const float* vals     = (const float*)d_in[3];
    const float* W1       = (const float*)d_in[4];
    const float* b1       = (const float*)d_in[5];
    const float* W2       = (const float*)d_in[6];
    const float* b2       = (const float*)d_in[7];

    float *x0p, *xap, *xbp;
    cudaGetSymbolAddress((void**)&x0p, g_x0);
    cudaGetSymbolAddress((void**)&xap, g_xa);
    cudaGetSymbolAddress((void**)&xbp, g_xb);

    // CSR build
    k_zero_deg<<<(NN + 255) / 256, 256>>>();
    k_hist<<<(NE + 255) / 256, 256>>>(row);
    k_scan1<<<SCAN_NB, SCAN_BLOCK>>>();
    k_scan2<<<1, 128>>>();
    k_scan3<<<(NN + 255) / 256, 256>>>();
    k_fill<<<(NE + 255) / 256, 256>>>(row, col, vals);

    // MLP head
    const int smem_bytes = (16384 + 2048 + 64 + 32 + 256 * FPAD) * sizeof(float);
    cudaFuncSetAttribute(k_mlp, cudaFuncAttributeMaxDynamicSharedMemorySize, smem_bytes);
    k_mlp<<<(NN + 255) / 256, 256, smem_bytes>>>(features, W1, b1, W2, b2);

    // 10 propagation steps, ping-pong; last writes d_out
    const int spmm_blocks = (NN * 32 + 255) / 256;   // warp per node
    const float* src = x0p;
    for (int it = 0; it < 10; it++) {
        float* dst = (it == 9) ? (float*)d_out : ((it % 2 == 0) ? xap : xbp);
        k_spmm<<<spmm_blocks, 256>>>(src, dst);
        src = dst;
    }
}

// round 2
// speedup vs baseline: 1.0690x; 1.0690x over previous
#include <cuda_runtime.h>
#include <cuda_bf16.h>

#define NN 100000
#define NE 1600000
#define NEP (NE + 8 * NN)     // padded-edge capacity
#define DIN 256
#define DHID 64
#define DOUT 32
#define SCAN_BLOCK 1024
#define SCAN_NB ((NN + SCAN_BLOCK - 1) / SCAN_BLOCK)   // 98

// ---------------- scratch (static device memory: allowed) ----------------
__device__ float  g_x0[NN * DOUT];
__device__ float  g_xa[NN * DOUT];
__device__ float  g_xb[NN * DOUT];
__device__ float2 g_cv[NEP];         // packed (col-as-int-bits, 0.9*val), padded per node
__device__ int    g_offs[NN + 1];    // padded CSR offsets (multiples of 8 per segment)
__device__ int    g_deg[NN];
__device__ int    g_incl[NN];
__device__ int    g_cursor[NN];
__device__ int    g_bsum[128];

// ---------------- CSR build ----------------
__global__ void k_zero_deg() {
    int i = blockIdx.x * blockDim.x + threadIdx.x;
    if (i < NN) g_deg[i] = 0;
}

__global__ void k_hist(const int* __restrict__ row) {
    int e = blockIdx.x * blockDim.x + threadIdx.x;
    if (e < NE) atomicAdd(&g_deg[row[e]], 1);
}

// scan of PADDED degrees: deg_p = (deg + 7) & ~7
__global__ void k_scan1() {
    __shared__ int s[SCAN_BLOCK];
    int t = threadIdx.x;
    int b = blockIdx.x;
    int i = b * SCAN_BLOCK + t;
    int v = (i < NN) ? ((g_deg[i] + 7) & ~7) : 0;
    s[t] = v;
    __syncthreads();
    #pragma unroll
    for (int off = 1; off < SCAN_BLOCK; off <<= 1) {
        int add = (t >= off) ? s[t - off] : 0;
        __syncthreads();
        s[t] += add;
        __syncthreads();
    }
    if (i < NN) g_incl[i] = s[t];
    if (t == SCAN_BLOCK - 1) g_bsum[b] = s[t];
}

__global__ void k_scan2() {
    __shared__ int s[128];
    int t = threadIdx.x;
    s[t] = (t < SCAN_NB) ? g_bsum[t] : 0;
    __syncthreads();
    if (t == 0) {
        int run = 0;
        for (int b = 0; b < SCAN_NB; b++) { int tmp = s[b]; s[b] = run; run += tmp; }
    }
    __syncthreads();
    if (t < SCAN_NB) g_bsum[t] = s[t];
}

__global__ void k_scan3() {
    int i = blockIdx.x * blockDim.x + threadIdx.x;
    if (i < NN) {
        int degp = (g_deg[i] + 7) & ~7;
        int inc = g_incl[i] + g_bsum[i >> 10];
        g_offs[i + 1] = inc;
        g_cursor[i]   = inc - degp;
        if (i == 0) g_offs[0] = 0;
    }
}

__global__ void k_fill(const int* __restrict__ row, const int* __restrict__ col,
                       const float* __restrict__ val) {
    int e = blockIdx.x * blockDim.x + threadIdx.x;
    if (e < NE) {
        int r = row[e];
        int p = atomicAdd(&g_cursor[r], 1);
        g_cv[p] = make_float2(__int_as_float(col[e]), 0.9f * val[e]);
    }
}

// zero the padding tail of each node's segment (col=0, val=0 sentinels)
__global__ void k_pad() {
    int i = blockIdx.x * blockDim.x + threadIdx.x;
    if (i < NN) {
        int start = g_offs[i + 1] - (((g_deg[i] + 7) & ~7)) + g_deg[i];
        int end   = g_offs[i + 1];
        for (int p = start; p < end; p++)
            g_cv[p] = make_float2(0.f, 0.f);
    }
}

// ---------------- MLP head: x0 = relu(F@W1 + b1)@W2 + b2 ----------------
#define FPAD 33
__global__ void __launch_bounds__(256)
k_mlp(const float* __restrict__ features,
      const float* __restrict__ W1, const float* __restrict__ b1,
      const float* __restrict__ W2, const float* __restrict__ b2) {
    extern __shared__ float sm[];
    float* w1s = sm;                      // 16384
    float* w2s = sm + 16384;              // 2048
    float* b1s = w2s + 2048;              // 64
    float* b2s = b1s + 64;                // 32
    float* fsm = b2s + 32;                // 256*33 = 8448

    const int t = threadIdx.x;
    const int node0 = blockIdx.x * 256;

    for (int i = t; i < DIN * DHID; i += 256) w1s[i] = W1[i];
    for (int i = t; i < DHID * DOUT; i += 256) w2s[i] = W2[i];
    if (t < DHID) b1s[t] = b1[t];
    if (t < DOUT) b2s[t] = b2[t];
    __syncthreads();

    const float4* w1s4 = (const float4*)w1s;
    const float4* w2s4 = (const float4*)w2s;

    float acc[DHID];
    #pragma unroll
    for (int i = 0; i < DHID; i++) acc[i] = 0.f;

    for (int c = 0; c < DIN / 32; c++) {
        const int k0 = c * 32;
        __syncthreads();
        #pragma unroll
        for (int r = 0; r < 8; r++) {
            int lin = r * 256 + t;
            int nd = lin >> 3;
            int kg = lin & 7;
            float4 f4 = make_float4(0.f, 0.f, 0.f, 0.f);
            if (node0 + nd < NN)
                f4 = *(const float4*)&features[(size_t)(node0 + nd) * DIN + k0 + kg * 4];
            float* dst = &fsm[nd * FPAD + kg * 4];
            dst[0] = f4.x; dst[1] = f4.y; dst[2] = f4.z; dst[3] = f4.w;
        }
        __syncthreads();

        #pragma unroll 4
        for (int kk = 0; kk < 32; kk++) {
            float f = fsm[t * FPAD + kk];
            #pragma unroll
            for (int w = 0; w < 16; w++) {
                float4 wv = w1s4[(k0 + kk) * 16 + w];
                acc[w * 4 + 0] += f * wv.x;
                acc[w * 4 + 1] += f * wv.y;
                acc[w * 4 + 2] += f * wv.z;
                acc[w * 4 + 3] += f * wv.w;
            }
        }
    }

    #pragma unroll
    for (int i = 0; i < DHID; i++) {
        float z = acc[i] + b1s[i];
        acc[i] = z > 0.f ? z : 0.f;
    }

    for (int jg = 0; jg < 8; jg++) {
        float4 sv = ((const float4*)b2s)[jg];
        #pragma unroll
        for (int l = 0; l < DHID; l++) {
            float4 wv = w2s4[l * 8 + jg];
            float h = acc[l];
            sv.x += h * wv.x; sv.y += h * wv.y;
            sv.z += h * wv.z; sv.w += h * wv.w;
        }
        float* dst = &fsm[t * FPAD + jg * 4];
        dst[0] = sv.x; dst[1] = sv.y; dst[2] = sv.z; dst[3] = sv.w;
    }
    __syncthreads();

    #pragma unroll
    for (int r = 0; r < 8; r++) {
        int lin = r * 256 + t;
        int nd = lin >> 3;
        int jg = lin & 7;
        if (node0 + nd < NN) {
            float4 o;
            const float* src = &fsm[nd * FPAD + jg * 4];
            o.x = src[0]; o.y = src[1]; o.z = src[2]; o.w = src[3];
            *(float4*)&g_x0[(size_t)(node0 + nd) * DOUT + jg * 4] = o;
        }
    }
}

// ---------------- propagation: dst = (A' @ src) + 0.1 * x0  (A' has 0.9 folded) --------
// warp per node, lane = output column. Edge descriptors are uniform broadcast loads;
// 8 independent row gathers in flight per iteration (padded trip count).
__global__ void __launch_bounds__(256)
k_spmm(const float* __restrict__ xsrc, float* __restrict__ xdst) {
    int gtid = blockIdx.x * blockDim.x + threadIdx.x;
    int node = gtid >> 5;
    int lane = gtid & 31;
    if (node >= NN) return;

    int p  = g_offs[node];
    int pe = g_offs[node + 1];
    float acc = 0.f;
    const float2* __restrict__ cv = g_cv;

    for (; p < pe; p += 8) {
        float2 c0 = __ldg(&cv[p + 0]);
        float2 c1 = __ldg(&cv[p + 1]);
        float2 c2 = __ldg(&cv[p + 2]);
        float2 c3 = __ldg(&cv[p + 3]);
        float2 c4 = __ldg(&cv[p + 4]);
        float2 c5 = __ldg(&cv[p + 5]);
        float2 c6 = __ldg(&cv[p + 6]);
        float2 c7 = __ldg(&cv[p + 7]);
        float g0 = __ldg(&xsrc[(size_t)__float_as_int(c0.x) * DOUT + lane]);
        float g1 = __ldg(&xsrc[(size_t)__float_as_int(c1.x) * DOUT + lane]);
        float g2 = __ldg(&xsrc[(size_t)__float_as_int(c2.x) * DOUT + lane]);
        float g3 = __ldg(&xsrc[(size_t)__float_as_int(c3.x) * DOUT + lane]);
        float g4 = __ldg(&xsrc[(size_t)__float_as_int(c4.x) * DOUT + lane]);
        float g5 = __ldg(&xsrc[(size_t)__float_as_int(c5.x) * DOUT + lane]);
        float g6 = __ldg(&xsrc[(size_t)__float_as_int(c6.x) * DOUT + lane]);
        float g7 = __ldg(&xsrc[(size_t)__float_as_int(c7.x) * DOUT + lane]);
        acc += c0.y * g0;
        acc += c1.y * g1;
        acc += c2.y * g2;
        acc += c3.y * g3;
        acc += c4.y * g4;
        acc += c5.y * g5;
        acc += c6.y * g6;
        acc += c7.y * g7;
    }
    xdst[(size_t)node * DOUT + lane] = acc + 0.1f * g_x0[(size_t)node * DOUT + lane];
}

// ---------------- launch ----------------
extern "C" void kernel_launch(void* const* d_in, const int* in_sizes, int n_in,
                              void* d_out, int out_size) {
    const float* features = (const float*)d_in[0];
    const int*   row      = (const int*)d_in[1];
    const int*   col      = (const int*)d_in[2];
    const float* vals     = (const float*)d_in[3];
    const float* W1       = (const float*)d_in[4];
    const float* b1       = (const float*)d_in[5];
    const float* W2       = (const float*)d_in[6];
    const float* b2       = (const float*)d_in[7];

    float *x0p, *xap, *xbp;
    cudaGetSymbolAddress((void**)&x0p, g_x0);
    cudaGetSymbolAddress((void**)&xap, g_xa);
    cudaGetSymbolAddress((void**)&xbp, g_xb);

    // CSR build (padded to multiples of 8 per node)
    k_zero_deg<<<(NN + 255) / 256, 256>>>();
    k_hist<<<(NE + 255) / 256, 256>>>(row);
    k_scan1<<<SCAN_NB, SCAN_BLOCK>>>();
    k_scan2<<<1, 128>>>();
    k_scan3<<<(NN + 255) / 256, 256>>>();
    k_fill<<<(NE + 255) / 256, 256>>>(row, col, vals);
    k_pad<<<(NN + 255) / 256, 256>>>();

    // MLP head
    const int smem_bytes = (16384 + 2048 + 64 + 32 + 256 * FPAD) * sizeof(float);
    cudaFuncSetAttribute(k_mlp, cudaFuncAttributeMaxDynamicSharedMemorySize, smem_bytes);
    k_mlp<<<(NN + 255) / 256, 256, smem_bytes>>>(features, W1, b1, W2, b2);

    // 10 propagation steps, ping-pong; last writes d_out
    const int spmm_blocks = (NN * 32 + 255) / 256;   // warp per node
    const float* src = x0p;
    for (int it = 0; it < 10; it++) {
        float* dst = (it == 9) ? (float*)d_out : ((it % 2 == 0) ? xap : xbp);
        k_spmm<<<spmm_blocks, 256>>>(src, dst);
        src = dst;
    }
}

// round 3
// speedup vs baseline: 1.3377x; 1.2514x over previous
#include <cuda_runtime.h>
#include <cuda_bf16.h>

#define NN 100000
#define NE 1600000
#define CAP 64                // bucket capacity per node (max degree headroom)
#define DIN 256
#define DHID 64
#define DOUT 32

// ---------------- scratch (static device memory: allowed) ----------------
__device__ float  g_x0[NN * DOUT];
__device__ float  g_xa[NN * DOUT];
__device__ float  g_xb[NN * DOUT];
__device__ float2 g_cv[(size_t)NN * CAP];   // bucketed (col-as-int-bits, 0.9*val)
__device__ int    g_deg[NN];

// ---------------- fill: bucketed scatter ----------------
__global__ void k_fill(const int* __restrict__ row, const int* __restrict__ col,
                       const float* __restrict__ val) {
    int e = blockIdx.x * blockDim.x + threadIdx.x;
    if (e < NE) {
        int r = row[e];
        int idx = atomicAdd(&g_deg[r], 1);
        g_cv[(size_t)r * CAP + idx] = make_float2(__int_as_float(col[e]), 0.9f * val[e]);
    }
}

// zero the padding tail (deg .. round8(deg)-1) with (col=0, val=0) sentinels
__global__ void k_pad() {
    int i = blockIdx.x * blockDim.x + threadIdx.x;
    if (i < NN) {
        int d = g_deg[i];
        int dp = (d + 7) & ~7;
        float2* b = &g_cv[(size_t)i * CAP];
        for (int p = d; p < dp; p++) b[p] = make_float2(0.f, 0.f);
    }
}

// ---------------- MLP head: x0 = relu(F@W1 + b1)@W2 + b2  (+ fused deg zeroing) --------
#define FPAD 33
__global__ void __launch_bounds__(256)
k_mlp(const float* __restrict__ features,
      const float* __restrict__ W1, const float* __restrict__ b1,
      const float* __restrict__ W2, const float* __restrict__ b2) {
    extern __shared__ float sm[];
    float* w1s = sm;                      // 16384
    float* w2s = sm + 16384;              // 2048
    float* b1s = w2s + 2048;              // 64
    float* b2s = b1s + 64;                // 32
    float* fsm = b2s + 32;                // 256*33 = 8448

    const int t = threadIdx.x;
    const int node0 = blockIdx.x * 256;

    // fused: zero degree counters for the CSR build that follows
    {
        int gt = node0 + t;
        if (gt < NN) g_deg[gt] = 0;
    }

    for (int i = t; i < DIN * DHID; i += 256) w1s[i] = W1[i];
    for (int i = t; i < DHID * DOUT; i += 256) w2s[i] = W2[i];
    if (t < DHID) b1s[t] = b1[t];
    if (t < DOUT) b2s[t] = b2[t];
    __syncthreads();

    const float4* w1s4 = (const float4*)w1s;
    const float4* w2s4 = (const float4*)w2s;

    float acc[DHID];
    #pragma unroll
    for (int i = 0; i < DHID; i++) acc[i] = 0.f;

    for (int c = 0; c < DIN / 32; c++) {
        const int k0 = c * 32;
        __syncthreads();
        #pragma unroll
        for (int r = 0; r < 8; r++) {
            int lin = r * 256 + t;
            int nd = lin >> 3;
            int kg = lin & 7;
            float4 f4 = make_float4(0.f, 0.f, 0.f, 0.f);
            if (node0 + nd < NN)
                f4 = *(const float4*)&features[(size_t)(node0 + nd) * DIN + k0 + kg * 4];
            float* dst = &fsm[nd * FPAD + kg * 4];
            dst[0] = f4.x; dst[1] = f4.y; dst[2] = f4.z; dst[3] = f4.w;
        }
        __syncthreads();

        #pragma unroll 4
        for (int kk = 0; kk < 32; kk++) {
            float f = fsm[t * FPAD + kk];
            #pragma unroll
            for (int w = 0; w < 16; w++) {
                float4 wv = w1s4[(k0 + kk) * 16 + w];
                acc[w * 4 + 0] += f * wv.x;
                acc[w * 4 + 1] += f * wv.y;
                acc[w * 4 + 2] += f * wv.z;
                acc[w * 4 + 3] += f * wv.w;
            }
        }
    }

    #pragma unroll
    for (int i = 0; i < DHID; i++) {
        float z = acc[i] + b1s[i];
        acc[i] = z > 0.f ? z : 0.f;
    }

    for (int jg = 0; jg < 8; jg++) {
        float4 sv = ((const float4*)b2s)[jg];
        #pragma unroll
        for (int l = 0; l < DHID; l++) {
            float4 wv = w2s4[l * 8 + jg];
            float h = acc[l];
            sv.x += h * wv.x; sv.y += h * wv.y;
            sv.z += h * wv.z; sv.w += h * wv.w;
        }
        float* dst = &fsm[t * FPAD + jg * 4];
        dst[0] = sv.x; dst[1] = sv.y; dst[2] = sv.z; dst[3] = sv.w;
    }
    __syncthreads();

    #pragma unroll
    for (int r = 0; r < 8; r++) {
        int lin = r * 256 + t;
        int nd = lin >> 3;
        int jg = lin & 7;
        if (node0 + nd < NN) {
            float4 o;
            const float* src = &fsm[nd * FPAD + jg * 4];
            o.x = src[0]; o.y = src[1]; o.z = src[2]; o.w = src[3];
            *(float4*)&g_x0[(size_t)(node0 + nd) * DOUT + jg * 4] = o;
        }
    }
}

// ---------------- propagation: dst = (A' @ src) + 0.1 * x0  (0.9 folded into A') ------
// 4 nodes per warp: grp = lane>>3 selects sub-node, lane8 = lane&7 covers 32 cols
// via float4. One LDG.128 gathers 4 edges' rows (one per group); one coalesced
// LDG.64 fetches 32 edge descriptors. Sentinel (col=0,val=0) edges keep the
// trip count uniform; they gather row 0 (L1-resident) with weight 0.
__global__ void __launch_bounds__(256)
k_spmm(const float* __restrict__ xsrc, float* __restrict__ xdst) {
    int gtid  = blockIdx.x * blockDim.x + threadIdx.x;
    int warp  = gtid >> 5;
    int lane  = threadIdx.x & 31;
    int grp   = lane >> 3;
    int lane8 = lane & 7;
    int node  = warp * 4 + grp;          // NN % 4 == 0, grid sized exactly
    if (node >= NN) return;

    int trip = (g_deg[node] + 7) >> 3;   // unroll-8 trips for this sub-node
    int mt = trip;
    mt = max(mt, __shfl_xor_sync(0xffffffffu, mt, 16));
    mt = max(mt, __shfl_xor_sync(0xffffffffu, mt, 8));

    const float2* __restrict__ bucket = &g_cv[(size_t)node * CAP];
    int p = lane8;                       // this lane's descriptor slot within bucket

    float4 acc = make_float4(0.f, 0.f, 0.f, 0.f);
    for (int t = 0; t < mt; t++) {
        float2 cv = make_float2(0.f, 0.f);
        if (t < trip) cv = __ldg(&bucket[p]);
        p += 8;
        #pragma unroll
        for (int j = 0; j < 8; j++) {
            int   c = __float_as_int(__shfl_sync(0xffffffffu, cv.x, (lane & 24) + j));
            float v = __shfl_sync(0xffffffffu, cv.y, (lane & 24) + j);
            float4 g = __ldg((const float4*)&xsrc[(size_t)c * DOUT + lane8 * 4]);
            acc.x += v * g.x;
            acc.y += v * g.y;
            acc.z += v * g.z;
            acc.w += v * g.w;
        }
    }

    const float4 x0 = *(const float4*)&g_x0[(size_t)node * DOUT + lane8 * 4];
    float4 o;
    o.x = acc.x + 0.1f * x0.x;
    o.y = acc.y + 0.1f * x0.y;
    o.z = acc.z + 0.1f * x0.z;
    o.w = acc.w + 0.1f * x0.w;
    *(float4*)&xdst[(size_t)node * DOUT + lane8 * 4] = o;
}

// ---------------- launch ----------------
extern "C" void kernel_launch(void* const* d_in, const int* in_sizes, int n_in,
                              void* d_out, int out_size) {
    const float* features = (const float*)d_in[0];
    const int*   row      = (const int*)d_in[1];
    const int*   col      = (const int*)d_in[2];
    const float* vals     = (const float*)d_in[3];
    const float* W1       = (const float*)d_in[4];
    const float* b1       = (const float*)d_in[5];
    const float* W2       = (const float*)d_in[6];
    const float* b2       = (const float*)d_in[7];

    float *x0p, *xap, *xbp;
    cudaGetSymbolAddress((void**)&x0p, g_x0);
    cudaGetSymbolAddress((void**)&xap, g_xa);
    cudaGetSymbolAddress((void**)&xbp, g_xb);

    // 1) MLP head (also zeroes per-node degree counters)
    const int smem_bytes = (16384 + 2048 + 64 + 32 + 256 * FPAD) * sizeof(float);
    cudaFuncSetAttribute(k_mlp, cudaFuncAttributeMaxDynamicSharedMemorySize, smem_bytes);
    k_mlp<<<(NN + 255) / 256, 256, smem_bytes>>>(features, W1, b1, W2, b2);

    // 2) bucketed CSR build + 3) pad tails to multiple of 8
    k_fill<<<(NE + 255) / 256, 256>>>(row, col, vals);
    k_pad<<<(NN + 255) / 256, 256>>>();

    // 4..13) 10 propagation steps, ping-pong; last writes d_out
    const int spmm_blocks = (NN / 4 * 32 + 255) / 256;   // 4 nodes per warp
    const float* src = x0p;
    for (int it = 0; it < 10; it++) {
        float* dst = (it == 9) ? (float*)d_out : ((it % 2 == 0) ? xap : xbp);
        k_spmm<<<spmm_blocks, 256>>>(src, dst);
        src = dst;
    }
}